// round 6
// baseline (speedup 1.0000x reference)
#include <cuda_runtime.h>
#include <cstdint>

// Masked cumsum along dim 1: out[b,:] = cumsum(where(mask, x, 0))
// B=256 rows, N=131072 cols, fp32 x, int32 mask.
//
// R6: chained tile scan. Each row = 8 tiles of 16384 elems; one CTA per tile
// -> 2048 CTAs (~6.9 waves of 296 occ-2 slots, 98.8% wave utilization vs
// 86.5% for 256 CTAs). Tickets map vt -> (row = vt % rows, k = vt / rows)
// [column-major], so tile k runs ~one wave after tile k-1: the distance-1
// carry flag is already published when needed -> no lookback, no spinning
// waves (the R3 failure). Flags carry {epoch_tag, float payload}; epoch from
// a never-reset ticket counter -> graph replays need no reset.
//
// Intra-tile: 4 sub-chunks of 4096 with the proven R5 machinery (warp-owned
// contiguous 256-float segments, 2 perfectly-coalesced float4/int4 rounds,
// lane scan -> 2 warp scans -> redundant-per-warp CTA scan, ONE barrier per
// sub-chunk, 1-deep prefetch, streaming hints). Carry published before the
// last sub-chunk's stores so the chain advances while stores drain.

#define CS_THREADS 512
#define CS_NWARPS  16
#define CS_CHUNK   4096                   // elems per sub-chunk (512 thr * 8)
#define SUBCHUNKS  4
#define CS_TILE    (CS_CHUNK * SUBCHUNKS) // 16384
#define CS_NCOLS   131072
#define CS_TPR     (CS_NCOLS / CS_TILE)   // 8 tiles per row
#define MAXTILES   2048                   // 256 rows * 8

__device__ unsigned long long g_ticket;           // never reset; epoch = ticket / grid
__device__ unsigned long long g_flags[MAXTILES];  // [31:0]=tag=(epoch<<1|1), [63:32]=float bits

__device__ __forceinline__ void st_release_u64(unsigned long long* p, unsigned long long v) {
    asm volatile("st.release.gpu.global.u64 [%0], %1;" :: "l"(p), "l"(v) : "memory");
}
__device__ __forceinline__ unsigned long long ld_acquire_u64(const unsigned long long* p) {
    unsigned long long v;
    asm volatile("ld.acquire.gpu.global.u64 %0, [%1];" : "=l"(v) : "l"(p) : "memory");
    return v;
}

__global__ __launch_bounds__(CS_THREADS, 2)
void masked_cumsum_chained(const float* __restrict__ x,
                           const int* __restrict__ mask,
                           float* __restrict__ out) {
    __shared__ float shW[2][CS_NWARPS];
    __shared__ float shBase;
    __shared__ unsigned long long shTicket;

    const int tid  = threadIdx.x;
    const int lane = tid & 31;
    const int warp = tid >> 5;

    // ---- ticket: monotone work assignment (deadlock-free chain) + epoch ----
    if (tid == 0) shTicket = atomicAdd(&g_ticket, 1ULL);
    __syncthreads();
    const unsigned long long t = shTicket;
    const unsigned ntiles = gridDim.x;                 // 2048
    const unsigned nrows  = ntiles / CS_TPR;           // 256
    const unsigned epoch  = (unsigned)(t / ntiles);
    const unsigned vt     = (unsigned)(t % ntiles);
    const unsigned row    = vt % nrows;                // column-major: tile k of a
    const unsigned k      = vt / nrows;                // row runs a wave after k-1
    const unsigned tag    = (epoch << 1) | 1u;

    // ---- pointers: warp owns a contiguous 256-float segment per sub-chunk ----
    const size_t base4 = (size_t)row * (CS_NCOLS / 4) + (size_t)k * (CS_TILE / 4);
    const float4* __restrict__ x4 = reinterpret_cast<const float4*>(x) + base4;
    const int4*   __restrict__ m4 = reinterpret_cast<const int4*>(mask) + base4;
    float4*       __restrict__ o4 = reinterpret_cast<float4*>(out) + base4;
    const int wbase = warp * 64 + lane;

    // Prefetch sub-chunk 0 (in flight while we wait on the carry flag)
    float4 pa0 = __ldcs(&x4[wbase]);
    float4 pa1 = __ldcs(&x4[wbase + 32]);
    int4   pm0 = __ldcs(&m4[wbase]);
    int4   pm1 = __ldcs(&m4[wbase + 32]);

    // ---- distance-1 chain: fetch predecessor's inclusive prefix ----
    if (tid == 0) {
        float b = 0.0f;
        if (k > 0) {
            const unsigned long long* f = &g_flags[vt - nrows];
            unsigned long long w = ld_acquire_u64(f);
            while ((unsigned)w != tag) { __nanosleep(32); w = ld_acquire_u64(f); }
            b = __uint_as_float((unsigned)(w >> 32));
        }
        shBase = b;
    }

    float carry = 0.0f;   // local (within-tile) running prefix
    float baseReg = 0.0f; // cross-tile base, read after first barrier

    #pragma unroll
    for (int s = 0; s < SUBCHUNKS; ++s) {
        const float4 xa0 = pa0, xa1 = pa1;
        const int4   ma0 = pm0, ma1 = pm1;
        if (s + 1 < SUBCHUNKS) {
            const int nb = (s + 1) * (CS_CHUNK / 4) + wbase;
            pa0 = __ldcs(&x4[nb]);
            pa1 = __ldcs(&x4[nb + 32]);
            pm0 = __ldcs(&m4[nb]);
            pm1 = __ldcs(&m4[nb + 32]);
        }

        float v[2][4];
        v[0][0] = ma0.x ? xa0.x : 0.f; v[0][1] = ma0.y ? xa0.y : 0.f;
        v[0][2] = ma0.z ? xa0.z : 0.f; v[0][3] = ma0.w ? xa0.w : 0.f;
        v[1][0] = ma1.x ? xa1.x : 0.f; v[1][1] = ma1.y ? xa1.y : 0.f;
        v[1][2] = ma1.z ? xa1.z : 0.f; v[1][3] = ma1.w ? xa1.w : 0.f;

        #pragma unroll
        for (int b = 0; b < 2; ++b)
            #pragma unroll
            for (int i = 1; i < 4; ++i) v[b][i] += v[b][i - 1];

        float lexcl[2], T[2];
        #pragma unroll
        for (int b = 0; b < 2; ++b) {
            const float sv = v[b][3];
            float incl = sv;
            #pragma unroll
            for (int d = 1; d < 32; d <<= 1) {
                float n = __shfl_up_sync(0xffffffffu, incl, d);
                if (lane >= d) incl += n;
            }
            lexcl[b] = incl - sv;
            T[b] = __shfl_sync(0xffffffffu, incl, 31);
        }
        const float warpTotal = T[0] + T[1];

        const int buf = s & 1;
        if (lane == 0) shW[buf][warp] = warpTotal;
        __syncthreads();

        // Redundant-per-warp CTA scan of the 16 warp totals (no 2nd barrier)
        float wv = (lane < CS_NWARPS) ? shW[buf][lane] : 0.f;
        float wincl = wv;
        #pragma unroll
        for (int d = 1; d < CS_NWARPS; d <<= 1) {
            float n = __shfl_up_sync(0xffffffffu, wincl, d);
            if (lane >= d) wincl += n;
        }
        const float wexcl      = __shfl_sync(0xffffffffu, wincl, warp) -
                                 __shfl_sync(0xffffffffu, wv,    warp);
        const float chunkTotal = __shfl_sync(0xffffffffu, wincl, CS_NWARPS - 1);

        if (s == 0) baseReg = shBase;   // tid0 wrote it before this barrier

        const float b0 = baseReg + carry + wexcl;
        carry += chunkTotal;

        // Publish inclusive prefix BEFORE the last sub-chunk's stores:
        // the chain advances while our stores drain.
        if (s == SUBCHUNKS - 1 && tid == 0) {
            const unsigned long long word =
                ((unsigned long long)__float_as_uint(baseReg + carry) << 32) | tag;
            st_release_u64(&g_flags[vt], word);
        }

        const float baseA = b0 + lexcl[0];
        const float baseB = b0 + T[0] + lexcl[1];
        const int ob = s * (CS_CHUNK / 4) + wbase;
        float4 oa, obv;
        oa.x  = v[0][0] + baseA; oa.y  = v[0][1] + baseA;
        oa.z  = v[0][2] + baseA; oa.w  = v[0][3] + baseA;
        obv.x = v[1][0] + baseB; obv.y = v[1][1] + baseB;
        obv.z = v[1][2] + baseB; obv.w = v[1][3] + baseB;
        __stcs(&o4[ob],      oa);
        __stcs(&o4[ob + 32], obv);
    }
}

extern "C" void kernel_launch(void* const* d_in, const int* in_sizes, int n_in,
                              void* d_out, int out_size) {
    const float* x    = (const float*)d_in[0];
    const int*   mask = (const int*)d_in[1];
    float*       out  = (float*)d_out;
    const int rows  = out_size / CS_NCOLS;   // 256
    const int tiles = rows * CS_TPR;         // 2048
    masked_cumsum_chained<<<tiles, CS_THREADS>>>(x, mask, out);
}

// round 7
// speedup vs baseline: 1.4300x; 1.4300x over previous
#include <cuda_runtime.h>
#include <cstdint>

// Masked cumsum along dim 1: out[b,:] = cumsum(where(mask, x, 0))
// B=256 rows, N=131072 cols, fp32 x, int32 mask.
//
// One persistent CTA per row, serial carry over 32 chunks of 4096 (proven R5
// structure: warp-owned contiguous 256-float segments, 2 perfectly-coalesced
// float4/int4 rounds, 1-deep prefetch, streaming hints, ONE barrier/chunk).
//
// R7: shorten the per-iteration critical path.
//  (a) CTA-level scan with NO shuffles: after the barrier every thread loads
//      all 16 warp totals via 4x LDS.128 (broadcast) and computes its warp's
//      exclusive prefix + chunk total with a SEL/FADD tree (~50cyc vs ~130cyc
//      of dependent SHFLs, lat 26 each).
//  (b) warp chunk-total via 5-step shfl_xor butterfly running ILP-parallel
//      with the two warp scans, so lane0's STS (feeding the loop-carried
//      carry chain) issues ~50cyc earlier.

#define CS_THREADS 512
#define CS_NWARPS  16
#define CS_CHUNK   4096                   // 512 thr * 8 elems
#define CS_NCOLS   131072
#define CS_ITERS   (CS_NCOLS / CS_CHUNK)  // 32

__global__ __launch_bounds__(CS_THREADS, 2)
void masked_cumsum_kernel(const float* __restrict__ x,
                          const int* __restrict__ mask,
                          float* __restrict__ out) {
    __shared__ __align__(16) float shW[2][CS_NWARPS];  // [buf][w] = warp w total

    const int row = blockIdx.x;
    const size_t roff4 = (size_t)row * (CS_NCOLS / 4);
    const float4* __restrict__ x4 = reinterpret_cast<const float4*>(x) + roff4;
    const int4*   __restrict__ m4 = reinterpret_cast<const int4*>(mask) + roff4;
    float4*       __restrict__ o4 = reinterpret_cast<float4*>(out) + roff4;

    const int tid  = threadIdx.x;
    const int lane = tid & 31;
    const int warp = tid >> 5;
    const int wq   = warp >> 2;   // quad index of this warp (0..3)
    const int wr   = warp & 3;    // position within quad
    // Warp w owns floats [w*256, w*256+256) of each chunk:
    // round r (0,1), lane l -> float4 index w*64 + r*32 + l (perfectly coalesced)
    const int wbase = warp * 64 + lane;

    float carry = 0.0f;

    // Prefetch chunk 0
    float4 pa0 = __ldcs(&x4[wbase]);
    float4 pa1 = __ldcs(&x4[wbase + 32]);
    int4   pm0 = __ldcs(&m4[wbase]);
    int4   pm1 = __ldcs(&m4[wbase + 32]);

    for (int it = 0; it < CS_ITERS; ++it) {
        const float4 xa0 = pa0, xa1 = pa1;
        const int4   ma0 = pm0, ma1 = pm1;
        // Issue next chunk's loads immediately; consumed next iteration.
        if (it + 1 < CS_ITERS) {
            const int nb = (it + 1) * (CS_CHUNK / 4) + wbase;
            pa0 = __ldcs(&x4[nb]);
            pa1 = __ldcs(&x4[nb + 32]);
            pm0 = __ldcs(&m4[nb]);
            pm1 = __ldcs(&m4[nb + 32]);
        }

        // Apply mask (each int32 is 0 or 1)
        float v[2][4];
        v[0][0] = ma0.x ? xa0.x : 0.f; v[0][1] = ma0.y ? xa0.y : 0.f;
        v[0][2] = ma0.z ? xa0.z : 0.f; v[0][3] = ma0.w ? xa0.w : 0.f;
        v[1][0] = ma1.x ? xa1.x : 0.f; v[1][1] = ma1.y ? xa1.y : 0.f;
        v[1][2] = ma1.z ? xa1.z : 0.f; v[1][3] = ma1.w ? xa1.w : 0.f;

        // Lane-local inclusive scans (2 independent rounds -> ILP)
        #pragma unroll
        for (int b = 0; b < 2; ++b)
            #pragma unroll
            for (int i = 1; i < 4; ++i) v[b][i] += v[b][i - 1];

        const float sA = v[0][3];
        const float sB = v[1][3];

        // (b) warp total via butterfly reduce — independent of the scans below,
        // so the STS feeding the carry chain issues as early as possible.
        float wtot = sA + sB;
        #pragma unroll
        for (int d = 16; d; d >>= 1) wtot += __shfl_xor_sync(0xffffffffu, wtot, d);
        const int buf = it & 1;
        if (lane == 0) shW[buf][warp] = wtot;

        // Warp inclusive scans per round (store-path only now)
        float lexcl[2], T0;
        {
            float ia = sA, ib = sB;
            #pragma unroll
            for (int d = 1; d < 32; d <<= 1) {
                float na = __shfl_up_sync(0xffffffffu, ia, d);
                float nb = __shfl_up_sync(0xffffffffu, ib, d);
                if (lane >= d) { ia += na; ib += nb; }
            }
            lexcl[0] = ia - sA;
            lexcl[1] = ib - sB;
            T0 = __shfl_sync(0xffffffffu, ia, 31);
        }

        __syncthreads();

        // (a) CTA scan with no shuffles: every thread loads all 16 warp totals
        // (4x LDS.128, broadcast) and computes its warp's exclusive prefix +
        // chunk total via a SEL/FADD tree. Uniform per warp -> no divergence.
        const float4* shq = reinterpret_cast<const float4*>(shW[buf]);
        const float4 q0 = shq[0], q1 = shq[1], q2 = shq[2], q3 = shq[3];
        const float s0 = (q0.x + q0.y) + (q0.z + q0.w);
        const float s1 = (q1.x + q1.y) + (q1.z + q1.w);
        const float s2 = (q2.x + q2.y) + (q2.z + q2.w);
        const float s3 = (q3.x + q3.y) + (q3.z + q3.w);
        const float chunkTotal = (s0 + s1) + (s2 + s3);

        const float quadBelow = (wq > 0 ? s0 : 0.f) + (wq > 1 ? s1 : 0.f) +
                                (wq > 2 ? s2 : 0.f);
        const float ax = (wq == 0) ? q0.x : (wq == 1) ? q1.x : (wq == 2) ? q2.x : q3.x;
        const float ay = (wq == 0) ? q0.y : (wq == 1) ? q1.y : (wq == 2) ? q2.y : q3.y;
        const float az = (wq == 0) ? q0.z : (wq == 1) ? q1.z : (wq == 2) ? q2.z : q3.z;
        const float inQuad = (wr > 0 ? ax : 0.f) + (wr > 1 ? ay : 0.f) +
                             (wr > 2 ? az : 0.f);
        const float wexcl = quadBelow + inQuad;

        const float base0 = carry + wexcl;
        carry += chunkTotal;

        const float baseA = base0 + lexcl[0];
        const float baseB = base0 + T0 + lexcl[1];
        const int ob = it * (CS_CHUNK / 4) + wbase;
        float4 oa, obv;
        oa.x  = v[0][0] + baseA; oa.y  = v[0][1] + baseA;
        oa.z  = v[0][2] + baseA; oa.w  = v[0][3] + baseA;
        obv.x = v[1][0] + baseB; obv.y = v[1][1] + baseB;
        obv.z = v[1][2] + baseB; obv.w = v[1][3] + baseB;
        __stcs(&o4[ob],      oa);
        __stcs(&o4[ob + 32], obv);
        // No trailing barrier: iter i+2's STS to this buf is fenced by iter i+1's bar.
    }
}

extern "C" void kernel_launch(void* const* d_in, const int* in_sizes, int n_in,
                              void* d_out, int out_size) {
    const float* x    = (const float*)d_in[0];
    const int*   mask = (const int*)d_in[1];
    float*       out  = (float*)d_out;
    const int rows = out_size / CS_NCOLS;   // 256
    masked_cumsum_kernel<<<rows, CS_THREADS>>>(x, mask, out);
}